// round 5
// baseline (speedup 1.0000x reference)
#include <cuda_runtime.h>

#define BATCH 16384
#define BAG   30
#define P     8          // positions per block
#define NT    256
#define GRID  (BATCH / P)

// Inputs (metadata order):
// 0: white_indices int32 [B*BAG]   2: black_indices int32 [B*BAG]
// 4: ft_white f32 [41025,256]      5: ft_black f32 [41025,256]
// 6: fc1_w f32 [32,512]  7: fc1_b  8: fc2_w f32 [32,32]  9: fc2_b
// 10: fc3_w f32 [1,32]  11: fc3_b     out: f32 [B]

__global__ __launch_bounds__(NT, 2)
void nnue_kernel(const int* __restrict__ wi,
                 const int* __restrict__ bi,
                 const float4* __restrict__ ftw,    // [NUM_EMB][64] float4
                 const float4* __restrict__ ftb,
                 const float4* __restrict__ fc1w,   // [32][128] float4
                 const float* __restrict__ fc1b,
                 const float4* __restrict__ fc2w,   // [32][8] float4
                 const float* __restrict__ fc2b,
                 const float* __restrict__ fc3w,
                 const float* __restrict__ fc3b,
                 float* __restrict__ out)
{
    __shared__ int    s_idx[P][2][BAG];
    __shared__ float4 s_x[P][128];     // concat(white,black) after relu, as float4
    __shared__ float  s_h1[P][32];

    const int tid  = threadIdx.x;
    const int lane = tid & 31;
    const int warp = tid >> 5;
    const int p0   = blockIdx.x * P;

    // ---- stage indices for the 8 positions ----
    for (int i = tid; i < P * 2 * BAG; i += NT) {
        const int pp  = i / (2 * BAG);
        const int r   = i % (2 * BAG);
        const int tbl = r / BAG;
        const int j   = r % BAG;
        s_idx[pp][tbl][j] = tbl ? bi[(p0 + pp) * BAG + j]
                                : wi[(p0 + pp) * BAG + j];
    }
    __syncthreads();

    // ---- EmbeddingBag gather (float4, both tables) ----
    // thread -> (c4 = float4 column 0..63, grp = 0..3); grp handles positions
    // {2g, 2g+1} for both tables. Whole warp shares grp -> uniform sidx reads.
    {
        const int c4  = tid & 63;
        const int grp = tid >> 6;
#pragma unroll
        for (int pp = 0; pp < 2; pp++) {
            const int pos = 2 * grp + pp;
            float4 aw = make_float4(0.f, 0.f, 0.f, 0.f);
            float4 ab = make_float4(0.f, 0.f, 0.f, 0.f);
#pragma unroll 6
            for (int j = 0; j < BAG; j++) {
                const int iw = s_idx[pos][0][j];
                const int ib = s_idx[pos][1][j];
                const float4 vw = __ldg(&ftw[(size_t)iw * 64 + c4]);
                const float4 vb = __ldg(&ftb[(size_t)ib * 64 + c4]);
                aw.x += vw.x; aw.y += vw.y; aw.z += vw.z; aw.w += vw.w;
                ab.x += vb.x; ab.y += vb.y; ab.z += vb.z; ab.w += vb.w;
            }
            aw.x = fmaxf(aw.x, 0.f); aw.y = fmaxf(aw.y, 0.f);
            aw.z = fmaxf(aw.z, 0.f); aw.w = fmaxf(aw.w, 0.f);
            ab.x = fmaxf(ab.x, 0.f); ab.y = fmaxf(ab.y, 0.f);
            ab.z = fmaxf(ab.z, 0.f); ab.w = fmaxf(ab.w, 0.f);
            s_x[pos][c4]      = aw;   // white -> x[0..255]
            s_x[pos][64 + c4] = ab;   // black -> x[256..511]
        }
    }

    // ---- FC1 weights -> registers (once per block, overlaps the barrier) ----
    // warp owns outputs 4*warp .. 4*warp+3; lane covers f4 indices lane+32k.
    float4 wreg[4][4];
    float  b1[4];
#pragma unroll
    for (int oo = 0; oo < 4; oo++) {
        const int o = 4 * warp + oo;
#pragma unroll
        for (int k = 0; k < 4; k++)
            wreg[oo][k] = __ldg(&fc1w[(size_t)o * 128 + lane + 32 * k]);
        b1[oo] = __ldg(&fc1b[o]);
    }
    __syncthreads();

    // ---- FC1: each warp computes its 4 outputs for all 8 positions ----
#pragma unroll
    for (int pos = 0; pos < P; pos++) {
        float4 xr[4];
#pragma unroll
        for (int k = 0; k < 4; k++)
            xr[k] = s_x[pos][lane + 32 * k];

        float part[4];
#pragma unroll
        for (int oo = 0; oo < 4; oo++) {
            float s = 0.f;
#pragma unroll
            for (int k = 0; k < 4; k++) {
                s += wreg[oo][k].x * xr[k].x;
                s += wreg[oo][k].y * xr[k].y;
                s += wreg[oo][k].z * xr[k].z;
                s += wreg[oo][k].w * xr[k].w;
            }
            part[oo] = s;
        }
#pragma unroll
        for (int off = 16; off > 0; off >>= 1) {
#pragma unroll
            for (int oo = 0; oo < 4; oo++)
                part[oo] += __shfl_xor_sync(0xffffffffu, part[oo], off);
        }
        if (lane == 0) {
#pragma unroll
            for (int oo = 0; oo < 4; oo++)
                s_h1[pos][4 * warp + oo] = fmaxf(part[oo] + b1[oo], 0.f);
        }
    }
    __syncthreads();

    // ---- FC2 (32->32, relu) + FC3 (32->1): warp w handles position w ----
    {
        const int pos = warp;
        const float* h = s_h1[pos];
        float s = __ldg(&fc2b[lane]);
        const float4* w2 = fc2w + (size_t)lane * 8;
#pragma unroll
        for (int k = 0; k < 8; k++) {
            const float4 w = __ldg(&w2[k]);
            s += w.x * h[4 * k + 0];
            s += w.y * h[4 * k + 1];
            s += w.z * h[4 * k + 2];
            s += w.w * h[4 * k + 3];
        }
        float v = fmaxf(s, 0.f) * __ldg(&fc3w[lane]);
#pragma unroll
        for (int off = 16; off > 0; off >>= 1)
            v += __shfl_xor_sync(0xffffffffu, v, off);
        if (lane == 0)
            out[p0 + pos] = v + __ldg(&fc3b[0]);
    }
}

extern "C" void kernel_launch(void* const* d_in, const int* in_sizes, int n_in,
                              void* d_out, int out_size)
{
    const int*    wiP   = (const int*)d_in[0];
    const int*    biP   = (const int*)d_in[2];
    const float4* ftw   = (const float4*)d_in[4];
    const float4* ftb   = (const float4*)d_in[5];
    const float4* fc1w  = (const float4*)d_in[6];
    const float*  fc1b  = (const float*)d_in[7];
    const float4* fc2w  = (const float4*)d_in[8];
    const float*  fc2b  = (const float*)d_in[9];
    const float*  fc3w  = (const float*)d_in[10];
    const float*  fc3b  = (const float*)d_in[11];
    float* out = (float*)d_out;

    nnue_kernel<<<GRID, NT>>>(wiP, biP, ftw, ftb, fc1w, fc1b,
                              fc2w, fc2b, fc3w, fc3b, out);
}

// round 7
// speedup vs baseline: 1.0689x; 1.0689x over previous
#include <cuda_runtime.h>
#include <cuda_fp16.h>

#define NUM_EMB 41025
#define BATCH   16384
#define BAG     30
#define P       8          // positions per block
#define NT      256
#define GRID    (BATCH / P)

#define ROW_U4  32                     // 256 halves = 32 uint4 per row
#define TBL_U4  (NUM_EMB * ROW_U4)     // 1,312,800 uint4 per table

// fp16 shadow tables (scratch): [0]=white, [1]=black. 21 MB each.
__device__ uint4 g_ft16[2][TBL_U4];

// ---------------------------------------------------------------------------
// Pre-pass: convert both f32 tables to fp16. 8 floats -> 8 halves per thread.
// ---------------------------------------------------------------------------
__global__ __launch_bounds__(256)
void cvt_kernel(const float4* __restrict__ ftw, const float4* __restrict__ ftb)
{
    const int i = blockIdx.x * blockDim.x + threadIdx.x;
    if (i >= 2 * TBL_U4) return;
    const int tbl = (i >= TBL_U4);
    const int j   = tbl ? (i - TBL_U4) : i;
    const float4* src = tbl ? ftb : ftw;

    const float4 a = __ldg(&src[2 * j]);
    const float4 b = __ldg(&src[2 * j + 1]);

    __half2 h0 = __floats2half2_rn(a.x, a.y);
    __half2 h1 = __floats2half2_rn(a.z, a.w);
    __half2 h2 = __floats2half2_rn(b.x, b.y);
    __half2 h3 = __floats2half2_rn(b.z, b.w);

    uint4 o;
    o.x = *reinterpret_cast<unsigned*>(&h0);
    o.y = *reinterpret_cast<unsigned*>(&h1);
    o.z = *reinterpret_cast<unsigned*>(&h2);
    o.w = *reinterpret_cast<unsigned*>(&h3);
    g_ft16[tbl][j] = o;
}

// ---------------------------------------------------------------------------
// Main kernel: gather fp16 rows (one LDG.128 per warp per row), fp32 accum,
// then FC1 (register-resident weights) + FC2 + FC3.
// ---------------------------------------------------------------------------
__global__ __launch_bounds__(NT, 2)
void nnue_kernel(const int* __restrict__ wi,
                 const int* __restrict__ bi,
                 const float4* __restrict__ fc1w,   // [32][128] float4
                 const float* __restrict__ fc1b,
                 const float4* __restrict__ fc2w,   // [32][8] float4
                 const float* __restrict__ fc2b,
                 const float* __restrict__ fc3w,
                 const float* __restrict__ fc3b,
                 float* __restrict__ out)
{
    __shared__ int    s_idx[P][2][BAG];
    __shared__ float4 s_x[P][128];     // concat(white,black) after relu
    __shared__ float  s_h1[P][32];

    const int tid  = threadIdx.x;
    const int lane = tid & 31;
    const int warp = tid >> 5;
    const int p0   = blockIdx.x * P;

    // ---- stage indices for the 8 positions ----
    for (int i = tid; i < P * 2 * BAG; i += NT) {
        const int pp  = i / (2 * BAG);
        const int r   = i % (2 * BAG);
        const int tbl = r / BAG;
        const int j   = r % BAG;
        s_idx[pp][tbl][j] = tbl ? bi[(p0 + pp) * BAG + j]
                                : wi[(p0 + pp) * BAG + j];
    }
    __syncthreads();

    // ---- gather: warp w owns position w; one LDG.128 covers a full row ----
    {
        float accW[8], accB[8];
#pragma unroll
        for (int k = 0; k < 8; k++) { accW[k] = 0.f; accB[k] = 0.f; }

        const uint4* tw = g_ft16[0];
        const uint4* tb = g_ft16[1];

#pragma unroll 5
        for (int j = 0; j < BAG; j++) {
            const int iw = s_idx[warp][0][j];   // warp-uniform
            const int ib = s_idx[warp][1][j];
            const uint4 vw = __ldg(&tw[(size_t)iw * ROW_U4 + lane]);
            const uint4 vb = __ldg(&tb[(size_t)ib * ROW_U4 + lane]);
            const __half2* hw = reinterpret_cast<const __half2*>(&vw);
            const __half2* hb = reinterpret_cast<const __half2*>(&vb);
#pragma unroll
            for (int k = 0; k < 4; k++) {
                const float2 fw = __half22float2(hw[k]);
                const float2 fb = __half22float2(hb[k]);
                accW[2 * k]     += fw.x;
                accW[2 * k + 1] += fw.y;
                accB[2 * k]     += fb.x;
                accB[2 * k + 1] += fb.y;
            }
        }
        // relu + store to smem. lane holds cols 8*lane..8*lane+7.
        float4 w0 = make_float4(fmaxf(accW[0],0.f), fmaxf(accW[1],0.f),
                                fmaxf(accW[2],0.f), fmaxf(accW[3],0.f));
        float4 w1 = make_float4(fmaxf(accW[4],0.f), fmaxf(accW[5],0.f),
                                fmaxf(accW[6],0.f), fmaxf(accW[7],0.f));
        float4 b0 = make_float4(fmaxf(accB[0],0.f), fmaxf(accB[1],0.f),
                                fmaxf(accB[2],0.f), fmaxf(accB[3],0.f));
        float4 b1 = make_float4(fmaxf(accB[4],0.f), fmaxf(accB[5],0.f),
                                fmaxf(accB[6],0.f), fmaxf(accB[7],0.f));
        s_x[warp][2 * lane]          = w0;   // white -> x[0..255]
        s_x[warp][2 * lane + 1]      = w1;
        s_x[warp][64 + 2 * lane]     = b0;   // black -> x[256..511]
        s_x[warp][64 + 2 * lane + 1] = b1;
    }

    // ---- FC1 weights -> registers (once per block) ----
    float4 wreg[4][4];
    float  b1r[4];
#pragma unroll
    for (int oo = 0; oo < 4; oo++) {
        const int o = 4 * warp + oo;
#pragma unroll
        for (int k = 0; k < 4; k++)
            wreg[oo][k] = __ldg(&fc1w[(size_t)o * 128 + lane + 32 * k]);
        b1r[oo] = __ldg(&fc1b[o]);
    }
    __syncthreads();

    // ---- FC1: each warp computes its 4 outputs for all 8 positions ----
#pragma unroll
    for (int pos = 0; pos < P; pos++) {
        float4 xr[4];
#pragma unroll
        for (int k = 0; k < 4; k++)
            xr[k] = s_x[pos][lane + 32 * k];

        float part[4];
#pragma unroll
        for (int oo = 0; oo < 4; oo++) {
            float s = 0.f;
#pragma unroll
            for (int k = 0; k < 4; k++) {
                s += wreg[oo][k].x * xr[k].x;
                s += wreg[oo][k].y * xr[k].y;
                s += wreg[oo][k].z * xr[k].z;
                s += wreg[oo][k].w * xr[k].w;
            }
            part[oo] = s;
        }
#pragma unroll
        for (int off = 16; off > 0; off >>= 1) {
#pragma unroll
            for (int oo = 0; oo < 4; oo++)
                part[oo] += __shfl_xor_sync(0xffffffffu, part[oo], off);
        }
        if (lane == 0) {
#pragma unroll
            for (int oo = 0; oo < 4; oo++)
                s_h1[pos][4 * warp + oo] = fmaxf(part[oo] + b1r[oo], 0.f);
        }
    }
    __syncthreads();

    // ---- FC2 (32->32, relu) + FC3 (32->1): warp w handles position w ----
    {
        const int pos = warp;
        const float* h = s_h1[pos];
        float s = __ldg(&fc2b[lane]);
        const float4* w2 = fc2w + (size_t)lane * 8;
#pragma unroll
        for (int k = 0; k < 8; k++) {
            const float4 w = __ldg(&w2[k]);
            s += w.x * h[4 * k + 0];
            s += w.y * h[4 * k + 1];
            s += w.z * h[4 * k + 2];
            s += w.w * h[4 * k + 3];
        }
        float v = fmaxf(s, 0.f) * __ldg(&fc3w[lane]);
#pragma unroll
        for (int off = 16; off > 0; off >>= 1)
            v += __shfl_xor_sync(0xffffffffu, v, off);
        if (lane == 0)
            out[p0 + pos] = v + __ldg(&fc3b[0]);
    }
}

extern "C" void kernel_launch(void* const* d_in, const int* in_sizes, int n_in,
                              void* d_out, int out_size)
{
    const int*    wiP   = (const int*)d_in[0];
    const int*    biP   = (const int*)d_in[2];
    const float4* ftw   = (const float4*)d_in[4];
    const float4* ftb   = (const float4*)d_in[5];
    const float4* fc1w  = (const float4*)d_in[6];
    const float*  fc1b  = (const float*)d_in[7];
    const float4* fc2w  = (const float4*)d_in[8];
    const float*  fc2b  = (const float*)d_in[9];
    const float*  fc3w  = (const float*)d_in[10];
    const float*  fc3b  = (const float*)d_in[11];
    float* outP = (float*)d_out;

    const int n_cvt = 2 * TBL_U4;
    cvt_kernel<<<(n_cvt + 255) / 256, 256>>>(ftw, ftb);
    nnue_kernel<<<GRID, NT>>>(wiP, biP, fc1w, fc1b,
                              fc2w, fc2b, fc3w, fc3b, outP);
}

// round 8
// speedup vs baseline: 1.1319x; 1.0589x over previous
#include <cuda_runtime.h>
#include <cuda_fp16.h>
#include <cstdint>

#define NUM_EMB 41025
#define BATCH   16384
#define BAG     30
#define P       8          // positions per block
#define NT      256
#define GRID    (BATCH / P)

#define ROW_U4  32                     // 256 halves = 32 uint4 per row
#define TBL_U4  (NUM_EMB * ROW_U4)     // 1,312,800 uint4 per table

// fp16 shadow tables (scratch): [0]=white, [1]=black. 21 MB each.
__device__ uint4 g_ft16[2][TBL_U4];

// ---- packed f32x2 helpers (Blackwell sm_103a) ----
__device__ __forceinline__ void add_f32x2(uint64_t& acc, uint64_t v) {
    asm("add.rn.f32x2 %0, %1, %2;" : "=l"(acc) : "l"(acc), "l"(v));
}
__device__ __forceinline__ void fma_f32x2(uint64_t& acc, uint64_t a, uint64_t b) {
    asm("fma.rn.f32x2 %0, %1, %2, %3;" : "=l"(acc) : "l"(a), "l"(b), "l"(acc));
}
__device__ __forceinline__ uint64_t h2_to_f32x2(__half2 h) {
    float2 f = __half22float2(h);
    uint64_t r;
    asm("mov.b64 %0, {%1, %2};" : "=l"(r) : "f"(f.x), "f"(f.y));
    return r;
}
__device__ __forceinline__ float2 unpack_f32x2(uint64_t v) {
    float2 f;
    asm("mov.b64 {%0, %1}, %2;" : "=f"(f.x), "=f"(f.y) : "l"(v));
    return f;
}

// ---------------------------------------------------------------------------
// Pre-pass: convert both f32 tables to fp16.
// ---------------------------------------------------------------------------
__global__ __launch_bounds__(256)
void cvt_kernel(const float4* __restrict__ ftw, const float4* __restrict__ ftb)
{
    const int i = blockIdx.x * blockDim.x + threadIdx.x;
    if (i >= 2 * TBL_U4) return;
    const int tbl = (i >= TBL_U4);
    const int j   = tbl ? (i - TBL_U4) : i;
    const float4* src = tbl ? ftb : ftw;

    const float4 a = __ldg(&src[2 * j]);
    const float4 b = __ldg(&src[2 * j + 1]);

    __half2 h0 = __floats2half2_rn(a.x, a.y);
    __half2 h1 = __floats2half2_rn(a.z, a.w);
    __half2 h2 = __floats2half2_rn(b.x, b.y);
    __half2 h3 = __floats2half2_rn(b.z, b.w);

    uint4 o;
    o.x = *reinterpret_cast<unsigned*>(&h0);
    o.y = *reinterpret_cast<unsigned*>(&h1);
    o.z = *reinterpret_cast<unsigned*>(&h2);
    o.w = *reinterpret_cast<unsigned*>(&h3);
    g_ft16[tbl][j] = o;
}

// ---------------------------------------------------------------------------
// Main kernel.
// ---------------------------------------------------------------------------
__global__ __launch_bounds__(NT, 2)
void nnue_kernel(const int* __restrict__ wi,
                 const int* __restrict__ bi,
                 const float4* __restrict__ fc1w,   // [32][128] float4
                 const float* __restrict__ fc1b,
                 const float4* __restrict__ fc2w,   // [32][8] float4
                 const float* __restrict__ fc2b,
                 const float* __restrict__ fc3w,
                 const float* __restrict__ fc3b,
                 float* __restrict__ out)
{
    __shared__ int    s_idx[P][2][BAG];
    __shared__ float4 s_x[P][128];     // concat(white,black) after relu
    __shared__ float  s_h1[P][32];

    const int tid  = threadIdx.x;
    const int lane = tid & 31;
    const int warp = tid >> 5;
    const int p0   = blockIdx.x * P;

    // ---- stage indices ----
    for (int i = tid; i < P * 2 * BAG; i += NT) {
        const int pp  = i / (2 * BAG);
        const int r   = i % (2 * BAG);
        const int tbl = r / BAG;
        const int j   = r % BAG;
        s_idx[pp][tbl][j] = tbl ? bi[(p0 + pp) * BAG + j]
                                : wi[(p0 + pp) * BAG + j];
    }
    __syncthreads();

    // ---- gather: warp w owns position w. fp16 rows, chunk-of-3 HADD2
    //      accumulation, merged into packed f32x2 accumulators. ----
    {
        uint64_t accW[4], accB[4];         // f32x2 accumulators (8 cols)
#pragma unroll
        for (int k = 0; k < 4; k++) { accW[k] = 0ull; accB[k] = 0ull; }

        const uint4* tw = g_ft16[0];
        const uint4* tb = g_ft16[1];
        const int* iw_p = s_idx[warp][0];
        const int* ib_p = s_idx[warp][1];

#pragma unroll 2
        for (int c = 0; c < 10; c++) {     // 10 chunks x 3 rows
            __half2 hsW[4], hsB[4];
            {
                const int iw = iw_p[3 * c];
                const int ib = ib_p[3 * c];
                const uint4 vw = __ldg(&tw[(size_t)iw * ROW_U4 + lane]);
                const uint4 vb = __ldg(&tb[(size_t)ib * ROW_U4 + lane]);
                const __half2* hw = reinterpret_cast<const __half2*>(&vw);
                const __half2* hb = reinterpret_cast<const __half2*>(&vb);
#pragma unroll
                for (int k = 0; k < 4; k++) { hsW[k] = hw[k]; hsB[k] = hb[k]; }
            }
#pragma unroll
            for (int jj = 1; jj < 3; jj++) {
                const int iw = iw_p[3 * c + jj];
                const int ib = ib_p[3 * c + jj];
                const uint4 vw = __ldg(&tw[(size_t)iw * ROW_U4 + lane]);
                const uint4 vb = __ldg(&tb[(size_t)ib * ROW_U4 + lane]);
                const __half2* hw = reinterpret_cast<const __half2*>(&vw);
                const __half2* hb = reinterpret_cast<const __half2*>(&vb);
#pragma unroll
                for (int k = 0; k < 4; k++) {
                    hsW[k] = __hadd2(hsW[k], hw[k]);
                    hsB[k] = __hadd2(hsB[k], hb[k]);
                }
            }
            // merge chunk into f32x2 accumulators
#pragma unroll
            for (int k = 0; k < 4; k++) {
                add_f32x2(accW[k], h2_to_f32x2(hsW[k]));
                add_f32x2(accB[k], h2_to_f32x2(hsB[k]));
            }
        }

        // relu + store to smem. lane holds cols 8*lane..8*lane+7.
        float aw[8], ab[8];
#pragma unroll
        for (int k = 0; k < 4; k++) {
            const float2 fw = unpack_f32x2(accW[k]);
            const float2 fb = unpack_f32x2(accB[k]);
            aw[2 * k]     = fmaxf(fw.x, 0.f);
            aw[2 * k + 1] = fmaxf(fw.y, 0.f);
            ab[2 * k]     = fmaxf(fb.x, 0.f);
            ab[2 * k + 1] = fmaxf(fb.y, 0.f);
        }
        s_x[warp][2 * lane]          = make_float4(aw[0], aw[1], aw[2], aw[3]);
        s_x[warp][2 * lane + 1]      = make_float4(aw[4], aw[5], aw[6], aw[7]);
        s_x[warp][64 + 2 * lane]     = make_float4(ab[0], ab[1], ab[2], ab[3]);
        s_x[warp][64 + 2 * lane + 1] = make_float4(ab[4], ab[5], ab[6], ab[7]);
    }

    // ---- FC1 weights -> registers as packed f32x2 (once per block) ----
    uint64_t wp[4][8];                 // 4 outputs x 8 f32x2 pairs
    float    b1r[4];
#pragma unroll
    for (int oo = 0; oo < 4; oo++) {
        const int o = 4 * warp + oo;
#pragma unroll
        for (int k = 0; k < 4; k++) {
            const float4 w = __ldg(&fc1w[(size_t)o * 128 + lane + 32 * k]);
            uint64_t lo, hi;
            asm("mov.b64 %0, {%1, %2};" : "=l"(lo) : "f"(w.x), "f"(w.y));
            asm("mov.b64 %0, {%1, %2};" : "=l"(hi) : "f"(w.z), "f"(w.w));
            wp[oo][2 * k]     = lo;
            wp[oo][2 * k + 1] = hi;
        }
        b1r[oo] = __ldg(&fc1b[o]);
    }
    __syncthreads();

    // ---- FC1: each warp computes its 4 outputs for all 8 positions ----
#pragma unroll
    for (int pos = 0; pos < P; pos++) {
        uint64_t xp[8];
#pragma unroll
        for (int k = 0; k < 4; k++) {
            const float4 x = s_x[pos][lane + 32 * k];
            asm("mov.b64 %0, {%1, %2};" : "=l"(xp[2 * k])     : "f"(x.x), "f"(x.y));
            asm("mov.b64 %0, {%1, %2};" : "=l"(xp[2 * k + 1]) : "f"(x.z), "f"(x.w));
        }
        float part[4];
#pragma unroll
        for (int oo = 0; oo < 4; oo++) {
            uint64_t acc = 0ull;
#pragma unroll
            for (int k = 0; k < 8; k++)
                fma_f32x2(acc, wp[oo][k], xp[k]);
            const float2 f = unpack_f32x2(acc);
            part[oo] = f.x + f.y;
        }
#pragma unroll
        for (int off = 16; off > 0; off >>= 1) {
#pragma unroll
            for (int oo = 0; oo < 4; oo++)
                part[oo] += __shfl_xor_sync(0xffffffffu, part[oo], off);
        }
        if (lane == 0) {
#pragma unroll
            for (int oo = 0; oo < 4; oo++)
                s_h1[pos][4 * warp + oo] = fmaxf(part[oo] + b1r[oo], 0.f);
        }
    }
    __syncthreads();

    // ---- FC2 (32->32, relu) + FC3 (32->1): warp w handles position w ----
    {
        const int pos = warp;
        const float* h = s_h1[pos];
        float s = __ldg(&fc2b[lane]);
        const float4* w2 = fc2w + (size_t)lane * 8;
#pragma unroll
        for (int k = 0; k < 8; k++) {
            const float4 w = __ldg(&w2[k]);
            s += w.x * h[4 * k + 0];
            s += w.y * h[4 * k + 1];
            s += w.z * h[4 * k + 2];
            s += w.w * h[4 * k + 3];
        }
        float v = fmaxf(s, 0.f) * __ldg(&fc3w[lane]);
#pragma unroll
        for (int off = 16; off > 0; off >>= 1)
            v += __shfl_xor_sync(0xffffffffu, v, off);
        if (lane == 0)
            out[p0 + pos] = v + __ldg(&fc3b[0]);
    }
}

extern "C" void kernel_launch(void* const* d_in, const int* in_sizes, int n_in,
                              void* d_out, int out_size)
{
    const int*    wiP   = (const int*)d_in[0];
    const int*    biP   = (const int*)d_in[2];
    const float4* ftw   = (const float4*)d_in[4];
    const float4* ftb   = (const float4*)d_in[5];
    const float4* fc1w  = (const float4*)d_in[6];
    const float*  fc1b  = (const float*)d_in[7];
    const float4* fc2w  = (const float4*)d_in[8];
    const float*  fc2b  = (const float*)d_in[9];
    const float*  fc3w  = (const float*)d_in[10];
    const float*  fc3b  = (const float*)d_in[11];
    float* outP = (float*)d_out;

    const int n_cvt = 2 * TBL_U4;
    cvt_kernel<<<(n_cvt + 255) / 256, 256>>>(ftw, ftb);
    nnue_kernel<<<GRID, NT>>>(wiP, biP, fc1w, fc1b,
                              fc2w, fc2b, fc3w, fc3b, outP);
}